// round 12
// baseline (speedup 1.0000x reference)
#include <cuda_runtime.h>
#include <cuda_bf16.h>
#include <cstdint>
#include <math.h>

#define NROWS 4096
#define D     128
#define AWORD 16
#define INV_TAU (1.0f/0.07f)
#define C1 ( 20.60992915555662f)   //  INV_TAU * log2(e)
#define C2 (-20.60992915555662f)
#define PB    68                   // bf16 smem row pitch in u32 (conflict-free)
#define LP    144                  // int8 smem row pitch in bytes (4g+tg bijective)

// ---------------- static device scratch ----------------
__device__ __nv_bfloat16 g_Zh[2 * NROWS * D];
__device__ char     g_L8[NROWS * 512];         // unpacked int8 labels (2 MB)
__device__ unsigned g_bits[NROWS * AWORD];     // kept for kfinal pmjj path (unused now)
__device__ int      g_cnt[NROWS];
__device__ unsigned g_pm[NROWS * (NROWS/32)];
__device__ float    g_se[NROWS], g_pv[NROWS];
__device__ int      g_npi[NROWS];
__device__ unsigned g_done;

// ---------------- helpers ----------------
__device__ __forceinline__ uint32_t smem_u32(const void* p) {
    uint32_t a;
    asm("{ .reg .u64 t; cvta.to.shared.u64 t, %1; cvt.u32.u64 %0, t; }" : "=r"(a) : "l"(p));
    return a;
}
__device__ __forceinline__ void cpa16(uint32_t dst, const void* src) {
    asm volatile("cp.async.cg.shared.global [%0], [%1], 16;" :: "r"(dst), "l"(src));
}
__device__ __forceinline__ void cpa8(uint32_t dst, const void* src) {
    asm volatile("cp.async.ca.shared.global [%0], [%1], 8;" :: "r"(dst), "l"(src));
}
#define CP_COMMIT() asm volatile("cp.async.commit_group;" ::: "memory")
#define CP_WAIT0()  asm volatile("cp.async.wait_group 0;" ::: "memory")
#define CP_WAIT1()  asm volatile("cp.async.wait_group 1;" ::: "memory")

__device__ __forceinline__ float ex2(float x) {
    float r;
    asm("ex2.approx.f32 %0, %1;" : "=f"(r) : "f"(x));
    return r;
}
__device__ __forceinline__ void ldsm_x4(uint32_t* r, uint32_t addr) {
    asm volatile("ldmatrix.sync.aligned.m8n8.x4.shared.b16 {%0,%1,%2,%3}, [%4];"
        : "=r"(r[0]), "=r"(r[1]), "=r"(r[2]), "=r"(r[3]) : "r"(addr));
}
__device__ __forceinline__ void mma_bf16(float* d, const uint32_t* a, const uint32_t* b) {
    asm volatile(
        "mma.sync.aligned.m16n8k16.row.col.f32.bf16.bf16.f32 "
        "{%0,%1,%2,%3}, {%4,%5,%6,%7}, {%8,%9}, {%0,%1,%2,%3};"
        : "+f"(d[0]), "+f"(d[1]), "+f"(d[2]), "+f"(d[3])
        : "r"(a[0]), "r"(a[1]), "r"(a[2]), "r"(a[3]), "r"(b[0]), "r"(b[1]));
}
__device__ __forceinline__ void mma_s8(int* d, const uint32_t* a, const uint32_t* b) {
    asm volatile(
        "mma.sync.aligned.m16n8k32.row.col.s32.s8.s8.s32 "
        "{%0,%1,%2,%3}, {%4,%5,%6,%7}, {%8,%9}, {%0,%1,%2,%3};"
        : "+r"(d[0]), "+r"(d[1]), "+r"(d[2]), "+r"(d[3])
        : "r"(a[0]), "r"(a[1]), "r"(a[2]), "r"(a[3]), "r"(b[0]), "r"(b[1]));
}

// ---------------- kernel 0: zero accumulators ----------------
__global__ void kzero() {
    int i = blockIdx.x * 256 + threadIdx.x;
    if (i == 0) g_done = 0;
    if (i < NROWS) { g_se[i] = 0.f; g_pv[i] = 0.f; g_npi[i] = 0; }
}

// ---------------- kernel 1: fused prep (normalize->bf16 / pack+unpack labels) ----------------
__global__ void kprep(const float* __restrict__ z1, const float* __restrict__ z2,
                      const int* __restrict__ labels) {
    const int tid  = threadIdx.x;
    const int wid  = tid >> 5;
    const int lane = tid & 31;

    if (blockIdx.x < 1024) {
        int r = blockIdx.x * 8 + wid;
        const float* src = (r < NROWS) ? (z1 + (size_t)r * D) : (z2 + (size_t)(r - NROWS) * D);
        float4 v = ((const float4*)src)[lane];
        float ss = v.x*v.x + v.y*v.y + v.z*v.z + v.w*v.w;
        #pragma unroll
        for (int o = 16; o; o >>= 1) ss += __shfl_xor_sync(0xffffffffu, ss, o);
        float inv = 1.0f / fmaxf(sqrtf(ss), 1e-12f);
        __nv_bfloat162 p0 = __floats2bfloat162_rn(v.x*inv, v.y*inv);
        __nv_bfloat162 p1 = __floats2bfloat162_rn(v.z*inv, v.w*inv);
        uint2 o2 = make_uint2(*(uint32_t*)&p0, *(uint32_t*)&p1);
        ((uint2*)g_Zh)[(size_t)r * 32 + lane] = o2;
    } else {
        int r = (blockIdx.x - 1024) * 8 + wid;
        const int* lp = labels + (size_t)r * 512;
        int cnt = 0; unsigned myw = 0;
        #pragma unroll
        for (int w = 0; w < AWORD; ++w) {
            int v = (lp[w * 32 + lane] != 0) ? 1 : 0;
            g_L8[(size_t)r * 512 + w * 32 + lane] = (char)v;
            unsigned word = __ballot_sync(0xffffffffu, v);
            if (lane == w) myw = word;
            cnt += __popc(word);
        }
        if (lane < AWORD) g_bits[r * AWORD + lane] = myw;
        if (lane == 0)    g_cnt[r] = cnt;
    }
}

// ---------------- kernel 2: jaccard pos mask via int8 MMA (exact) ----------------
// grid (32,32): block computes 128(j) x 128(i) tile. 512 threads, 16 warps (4m x 4n),
// warp tile 32x32, K=512 in 4 chunks of 128 int8.
// pos <=> inter>0 && (inter<<26) >= 20132659*union   (bit-identical to __fdiv_rn>=0.3f)
__global__ void __launch_bounds__(512) kjacc2() {
    __shared__ char sA[128 * LP];
    __shared__ char sB[128 * LP];
    __shared__ int  scj[128], sci[128];

    const int tid  = threadIdx.x;
    const int lane = tid & 31, wid = tid >> 5;
    const int wm   = wid >> 2, wn = wid & 3;
    const int g    = lane >> 2, tg = lane & 3;
    const int jb   = blockIdx.y, ib = blockIdx.x;

    if (tid < 128) { scj[tid] = g_cnt[jb * 128 + tid]; sci[tid] = g_cnt[ib * 128 + tid]; }

    int d[2][4][4];
    #pragma unroll
    for (int mf = 0; mf < 2; ++mf)
        #pragma unroll
        for (int nf = 0; nf < 4; ++nf)
            #pragma unroll
            for (int q = 0; q < 4; ++q) d[mf][nf][q] = 0;

    const char* Asrc = g_L8 + (size_t)jb * 128 * 512;
    const char* Bsrc = g_L8 + (size_t)ib * 128 * 512;
    uint32_t sa = smem_u32(sA), sbb = smem_u32(sB);

    #pragma unroll 1
    for (int kc = 0; kc < 4; ++kc) {
        __syncthreads();
        #pragma unroll
        for (int it = 0; it < 2; ++it) {
            int idx = it * 512 + tid;           // 0..1023
            int r = idx >> 3, c16 = idx & 7;    // 8 x 16B per 128B row-chunk
            cpa16(sa  + r * LP + c16 * 16, Asrc + (size_t)r * 512 + kc * 128 + c16 * 16);
            cpa16(sbb + r * LP + c16 * 16, Bsrc + (size_t)r * 512 + kc * 128 + c16 * 16);
        }
        CP_COMMIT(); CP_WAIT0();
        __syncthreads();

        #pragma unroll
        for (int ks = 0; ks < 4; ++ks) {
            const int k0 = ks * 32;
            uint32_t a[2][4];
            #pragma unroll
            for (int mf = 0; mf < 2; ++mf) {
                uint32_t base = sa + (wm * 32 + mf * 16 + g) * LP + k0 + tg * 4;
                a[mf][0] = *(const uint32_t*)(sA + (base - sa));
                a[mf][1] = *(const uint32_t*)(sA + (base - sa) + 8 * LP);
                a[mf][2] = *(const uint32_t*)(sA + (base - sa) + 16);
                a[mf][3] = *(const uint32_t*)(sA + (base - sa) + 8 * LP + 16);
            }
            #pragma unroll
            for (int nf = 0; nf < 4; ++nf) {
                uint32_t boff = (wn * 32 + nf * 8 + g) * LP + k0 + tg * 4;
                uint32_t b[2] = { *(const uint32_t*)(sB + boff),
                                  *(const uint32_t*)(sB + boff + 16) };
                mma_s8(d[0][nf], a[0], b);
                mma_s8(d[1][nf], a[1], b);
            }
        }
    }
    __syncthreads();

    // ---- epilogue: threshold test + pm word build + npi ----
    #pragma unroll
    for (int mf = 0; mf < 2; ++mf) {
        #pragma unroll
        for (int h = 0; h < 2; ++h) {
            const int rl = wm * 32 + mf * 16 + h * 8 + g;
            const int sj = scj[rl];
            unsigned wbits = 0;
            #pragma unroll
            for (int nf = 0; nf < 4; ++nf) {
                #pragma unroll
                for (int q = 0; q < 2; ++q) {
                    const int cl    = wn * 32 + nf * 8 + tg * 2 + q;
                    const int inter = d[mf][nf][h * 2 + q];
                    const int u     = sj + sci[cl] - inter;
                    bool pos = (inter > 0) &&
                               (((long long)inter << 26) >= 20132659LL * (long long)u);
                    wbits |= (pos ? 1u : 0u) << (nf * 8 + tg * 2 + q);
                }
            }
            wbits |= __shfl_xor_sync(0xffffffffu, wbits, 1);
            wbits |= __shfl_xor_sync(0xffffffffu, wbits, 2);
            if (tg == 0) {
                g_pm[(size_t)(jb * 128 + rl) * 128 + ib * 4 + wn] = wbits;
                atomicAdd(&g_npi[jb * 128 + rl], __popc(wbits));
            }
        }
    }
}

// ---------------- kernel 3: bf16 mma GEMM — ldmatrix + 3-stage pipeline ----------------
#define SM_A     0
#define SM_B     8704
#define BSTRIDE  4352
#define SM_PM    21760
#define PMSTRIDE 256
#define SMEM_U32 22528

__device__ __forceinline__ void ld_tileA(uint32_t sb, int jb, int tid) {
    const uint32_t* Asrc = (const uint32_t*)g_Zh + (size_t)jb * 128 * 64;
    #pragma unroll
    for (int it = 0; it < 8; ++it) {
        int idx = it * 256 + tid;
        int r = idx >> 4, gr = idx & 15;
        cpa16(sb + (uint32_t)(r * PB + gr * 4) * 4u, Asrc + r * 64 + gr * 4);
    }
}
__device__ __forceinline__ void ld_tileB(uint32_t sb, int buf, int ct, int jb, int tid) {
    const uint32_t* Bsrc = (const uint32_t*)g_Zh + (size_t)ct * 64 * 64;
    uint32_t bo = sb + (SM_B + buf * BSTRIDE) * 4u;
    #pragma unroll
    for (int it = 0; it < 4; ++it) {
        int idx = it * 256 + tid;
        int r = idx >> 4, gr = idx & 15;
        cpa16(bo + (uint32_t)(r * PB + gr * 4) * 4u, Bsrc + r * 64 + gr * 4);
    }
    if (tid < 128)
        cpa8(sb + (SM_PM + buf * PMSTRIDE + tid * 2) * 4u,
             g_pm + (size_t)(jb * 128 + tid) * 128 + (ct & 63) * 2);
}

__global__ void __launch_bounds__(256, 2) kmain(float* __restrict__ out) {
    extern __shared__ uint32_t sm32[];
    const int tid  = threadIdx.x;
    const int lane = tid & 31, wid = tid >> 5;
    const int wm   = wid >> 1, wn = wid & 1;
    const int g    = lane >> 2, tg = lane & 3;

    const int jb  = blockIdx.x >> 3;
    const int ct0 = (blockIdx.x & 7) * 16;

    uint32_t sb = smem_u32(sm32);

    const int grp = lane >> 3, lrow = lane & 7;
    const uint32_t addrA0 = sb + ((wm * 32 + (grp & 1) * 8 + lrow) * PB + (grp >> 1) * 4) * 4u;
    const uint32_t addrA1 = addrA0 + 16 * PB * 4u;
    const uint32_t boffB  = ((wn * 32 + (grp >> 1) * 8 + lrow) * PB + (grp & 1) * 4) * 4u;

    ld_tileA(sb, jb, tid);
    ld_tileB(sb, 0, ct0, jb, tid);
    CP_COMMIT();
    ld_tileB(sb, 1, ct0 + 1, jb, tid);
    CP_COMMIT();
    CP_WAIT1();
    __syncthreads();

    float se[4] = {0,0,0,0}, pv[4] = {0,0,0,0};

    int buf = 0;
    #pragma unroll 1
    for (int t = 0; t < 16; ++t) {
        const int ct = ct0 + t;
        if (t + 2 < 16) { ld_tileB(sb, (buf + 2) % 3, ct + 2, jb, tid); CP_COMMIT(); }

        float d[2][4][4];
        #pragma unroll
        for (int mf = 0; mf < 2; ++mf)
            #pragma unroll
            for (int nf = 0; nf < 4; ++nf)
                #pragma unroll
                for (int q = 0; q < 4; ++q) d[mf][nf][q] = 0.0f;

        const uint32_t addrB0 = sb + (SM_B + buf * BSTRIDE) * 4u + boffB;
        const uint32_t addrB1 = addrB0 + 16 * PB * 4u;

        #pragma unroll
        for (int ks = 0; ks < 8; ++ks) {
            uint32_t a0[4], a1[4], bA[4], bB[4];
            ldsm_x4(a0, addrA0 + ks * 32u);
            ldsm_x4(a1, addrA1 + ks * 32u);
            ldsm_x4(bA, addrB0 + ks * 32u);
            ldsm_x4(bB, addrB1 + ks * 32u);
            mma_bf16(d[0][0], a0, bA + 0);
            mma_bf16(d[0][1], a0, bA + 2);
            mma_bf16(d[0][2], a0, bB + 0);
            mma_bf16(d[0][3], a0, bB + 2);
            mma_bf16(d[1][0], a1, bA + 0);
            mma_bf16(d[1][1], a1, bA + 2);
            mma_bf16(d[1][2], a1, bB + 0);
            mma_bf16(d[1][3], a1, bB + 2);
        }

        const unsigned* pmS = sm32 + SM_PM + buf * PMSTRIDE;
        const int c0 = ct * 64;
        #pragma unroll
        for (int mf = 0; mf < 2; ++mf) {
            #pragma unroll
            for (int h = 0; h < 2; ++h) {
                const int rl   = wm * 32 + mf * 16 + h * 8 + g;
                const int jr   = jb * 128 + rl;
                const int jaug = jr + NROWS;
                const int ai   = mf * 2 + h;
                float a_se = 0.f, a_pv = 0.f;
                #pragma unroll
                for (int nf = 0; nf < 4; ++nf) {
                    const int cl = wn * 32 + nf * 8 + tg * 2;
                    const unsigned w = pmS[rl * 2 + (cl >> 5)];
                    #pragma unroll
                    for (int q = 0; q < 2; ++q) {
                        const int cg = c0 + cl + q;
                        float v = d[mf][nf][h * 2 + q];
                        float e = ex2(fmaf(v, C1, C2));
                        bool pos = (((w >> ((cl + q) & 31)) & 1u) != 0u) | (cg == jaug);
                        if (cg != jr) {
                            a_se += e;
                            if (pos) a_pv += v;
                        }
                    }
                }
                se[ai] += a_se; pv[ai] += a_pv;
            }
        }

        if (t + 2 < 16) CP_WAIT1();
        else            CP_WAIT0();
        __syncthreads();
        buf = (buf + 1) % 3;
    }

    #pragma unroll
    for (int ai = 0; ai < 4; ++ai) {
        float a = se[ai], b = pv[ai];
        a += __shfl_xor_sync(0xffffffffu, a, 1); a += __shfl_xor_sync(0xffffffffu, a, 2);
        b += __shfl_xor_sync(0xffffffffu, b, 1); b += __shfl_xor_sync(0xffffffffu, b, 2);
        if (tg == 0) {
            int row = jb * 128 + wm * 32 + (ai >> 1) * 16 + (ai & 1) * 8 + g;
            atomicAdd(&g_se[row], a);
            atomicAdd(&g_pv[row], b);
        }
    }

    __threadfence();
    __syncthreads();
    __shared__ unsigned ticket;
    if (tid == 0) ticket = atomicAdd(&g_done, 1u);
    __syncthreads();
    if (ticket == 255) {
        __shared__ float red[256];
        float s = 0.0f;
        for (int i = tid; i < NROWS; i += 256) {
            unsigned pmjj = (g_pm[(size_t)i * 128 + (i >> 5)] >> (i & 31)) & 1u;
            float np = (float)(2 * (g_npi[i] - (int)pmjj) + 1);   // >= 1
            float ps = INV_TAU * (g_pv[i] - np);
            s += -(ps - np * logf(g_se[i] + 1e-8f)) / np;
        }
        red[tid] = s;
        __syncthreads();
        for (int o = 128; o; o >>= 1) {
            if (tid < o) red[tid] += red[tid + o];
            __syncthreads();
        }
        if (tid == 0) out[0] = red[0] / (float)NROWS;
    }
}

// ---------------- launch ----------------
extern "C" void kernel_launch(void* const* d_in, const int* in_sizes, int n_in,
                              void* d_out, int out_size) {
    const float* z1     = (const float*)d_in[0];
    const float* z2     = (const float*)d_in[1];
    const int*   labels = (const int*)d_in[2];
    float* out = (float*)d_out;

    cudaFuncSetAttribute(kmain, cudaFuncAttributeMaxDynamicSharedMemorySize,
                         SMEM_U32 * 4);

    kzero<<<16, 256>>>();
    kprep<<<1536, 256>>>(z1, z2, labels);
    kjacc2<<<dim3(32, 32), 512>>>();
    kmain<<<256, 256, SMEM_U32 * 4>>>(out);   // ncu profiles launch index 3 = kmain
}

// round 13
// speedup vs baseline: 1.7648x; 1.7648x over previous
#include <cuda_runtime.h>
#include <cuda_bf16.h>
#include <cstdint>
#include <math.h>

#define NROWS 4096
#define D     128
#define AWORD 16
#define INV_TAU (1.0f/0.07f)
#define C1 ( 20.60992915555662f)   //  INV_TAU * log2(e)
#define C2 (-20.60992915555662f)
#define PB    68                   // smem row pitch in u32 (conflict-free)

// ---------------- static device scratch ----------------
__device__ __nv_bfloat16 g_Zh[2 * NROWS * D];
__device__ unsigned g_bits[NROWS * AWORD];
__device__ int      g_cnt[NROWS];
__device__ unsigned g_pm[NROWS * (NROWS/32)];
__device__ float    g_se[NROWS], g_pv[NROWS];
__device__ int      g_npi[NROWS];
__device__ unsigned g_done;

// ---------------- helpers ----------------
__device__ __forceinline__ uint32_t smem_u32(const void* p) {
    uint32_t a;
    asm("{ .reg .u64 t; cvta.to.shared.u64 t, %1; cvt.u32.u64 %0, t; }" : "=r"(a) : "l"(p));
    return a;
}
__device__ __forceinline__ void cpa16(uint32_t dst, const void* src) {
    asm volatile("cp.async.cg.shared.global [%0], [%1], 16;" :: "r"(dst), "l"(src));
}
__device__ __forceinline__ void cpa8(uint32_t dst, const void* src) {
    asm volatile("cp.async.ca.shared.global [%0], [%1], 8;" :: "r"(dst), "l"(src));
}
#define CP_COMMIT() asm volatile("cp.async.commit_group;" ::: "memory")
#define CP_WAIT0()  asm volatile("cp.async.wait_group 0;" ::: "memory")
#define CP_WAIT1()  asm volatile("cp.async.wait_group 1;" ::: "memory")

__device__ __forceinline__ float ex2(float x) {
    float r;
    asm("ex2.approx.f32 %0, %1;" : "=f"(r) : "f"(x));
    return r;
}
__device__ __forceinline__ void ldsm_x4(uint32_t* r, uint32_t addr) {
    asm volatile("ldmatrix.sync.aligned.m8n8.x4.shared.b16 {%0,%1,%2,%3}, [%4];"
        : "=r"(r[0]), "=r"(r[1]), "=r"(r[2]), "=r"(r[3]) : "r"(addr));
}
__device__ __forceinline__ void mma_bf16(float* d, const uint32_t* a, const uint32_t* b) {
    asm volatile(
        "mma.sync.aligned.m16n8k16.row.col.f32.bf16.bf16.f32 "
        "{%0,%1,%2,%3}, {%4,%5,%6,%7}, {%8,%9}, {%0,%1,%2,%3};"
        : "+f"(d[0]), "+f"(d[1]), "+f"(d[2]), "+f"(d[3])
        : "r"(a[0]), "r"(a[1]), "r"(a[2]), "r"(a[3]), "r"(b[0]), "r"(b[1]));
}

// ---------------- kernel 1: fused prep (normalize / pack / zero) ----------------
__global__ void kprep(const float* __restrict__ z1, const float* __restrict__ z2,
                      const int* __restrict__ labels) {
    const int tid  = threadIdx.x;
    const int wid  = tid >> 5;
    const int lane = tid & 31;
    if (blockIdx.x == 0 && tid == 0) g_done = 0;

    if (blockIdx.x < 1024) {
        int r = blockIdx.x * 8 + wid;
        const float* src = (r < NROWS) ? (z1 + (size_t)r * D) : (z2 + (size_t)(r - NROWS) * D);
        float4 v = ((const float4*)src)[lane];
        float ss = v.x*v.x + v.y*v.y + v.z*v.z + v.w*v.w;
        #pragma unroll
        for (int o = 16; o; o >>= 1) ss += __shfl_xor_sync(0xffffffffu, ss, o);
        float inv = 1.0f / fmaxf(sqrtf(ss), 1e-12f);
        __nv_bfloat162 p0 = __floats2bfloat162_rn(v.x*inv, v.y*inv);
        __nv_bfloat162 p1 = __floats2bfloat162_rn(v.z*inv, v.w*inv);
        uint2 o2 = make_uint2(*(uint32_t*)&p0, *(uint32_t*)&p1);
        ((uint2*)g_Zh)[(size_t)r * 32 + lane] = o2;
    } else {
        int b2 = blockIdx.x - 1024;
        int r  = b2 * 8 + wid;
        int gidx = b2 * 256 + tid;
        if (gidx < NROWS) { g_se[gidx] = 0.f; g_pv[gidx] = 0.f; g_npi[gidx] = 0; }
        const int* lp = labels + (size_t)r * 512;
        int cnt = 0; unsigned myw = 0;
        #pragma unroll
        for (int w = 0; w < AWORD; ++w) {
            unsigned word = __ballot_sync(0xffffffffu, lp[w * 32 + lane] != 0);
            if (lane == w) myw = word;
            cnt += __popc(word);
        }
        if (lane < AWORD) g_bits[r * AWORD + lane] = myw;
        if (lane == 0)    g_cnt[r] = cnt;
    }
}

// ---------------- kernel 2: jaccard pos mask + row popcounts (R11, proven) ----------------
__global__ void __launch_bounds__(128) kjacc() {
    int rem = blockIdx.x, jb = 0;
    while (rem >= 32 - jb) { rem -= 32 - jb; ++jb; }
    int ib = jb + rem;

    __shared__ unsigned sib[128 * AWORD];
    __shared__ int      sci[128];

    int tid  = threadIdx.x;
    int lane = tid & 31, wid = tid >> 5;

    uint4 jr4[4];
    #pragma unroll
    for (int q = 0; q < 4; ++q)
        jr4[q] = ((const uint4*)(g_bits + (size_t)(jb*128 + tid) * AWORD))[q];
    const unsigned* jr = (const unsigned*)jr4;
    int sj = g_cnt[jb*128 + tid];
    #pragma unroll
    for (int q = 0; q < 4; ++q)
        ((uint4*)sib)[q * 128 + tid] = ((const uint4*)(g_bits + (size_t)ib * 128 * AWORD))[q * 128 + tid];
    sci[tid] = g_cnt[ib*128 + tid];
    __syncthreads();

    unsigned myword = 0;
    unsigned tw[4];
    int pcmy = 0;
    #pragma unroll 2
    for (int i0 = 0; i0 < 128; i0 += 2) {
        const unsigned* iwA = sib + i0 * AWORD;
        const unsigned* iwB = iwA + AWORD;
        int a0=0, a1=0, a2=0, a3=0, b0=0, b1=0, b2=0, b3=0;
        #pragma unroll
        for (int w = 0; w < 4; ++w) {
            a0 += __popc(jr[w]      & iwA[w]);
            a1 += __popc(jr[w + 4]  & iwA[w + 4]);
            a2 += __popc(jr[w + 8]  & iwA[w + 8]);
            a3 += __popc(jr[w + 12] & iwA[w + 12]);
            b0 += __popc(jr[w]      & iwB[w]);
            b1 += __popc(jr[w + 4]  & iwB[w + 4]);
            b2 += __popc(jr[w + 8]  & iwB[w + 8]);
            b3 += __popc(jr[w + 12] & iwB[w + 12]);
        }
        int iA = (a0 + a1) + (a2 + a3);
        int iB = (b0 + b1) + (b2 + b3);
        long long uA = (long long)(sj + sci[i0]     - iA);
        long long uB = (long long)(sj + sci[i0 + 1] - iB);
        bool posA = (iA > 0) && (((long long)iA << 26) >= 20132659LL * uA);
        bool posB = (iB > 0) && (((long long)iB << 26) >= 20132659LL * uB);
        myword |= (posA ? 1u : 0u) << (i0 & 31);
        myword |= (posB ? 1u : 0u) << ((i0 + 1) & 31);
        unsigned balA = __ballot_sync(0xffffffffu, posA);
        unsigned balB = __ballot_sync(0xffffffffu, posB);
        if ((i0 & 31) == lane)       tw[i0 >> 5] = balA;
        if (((i0 + 1) & 31) == lane) tw[i0 >> 5] = balB;
        if ((i0 & 31) == 30) {
            g_pm[(size_t)(jb*128 + tid) * 128 + ib*4 + (i0 >> 5)] = myword;
            pcmy += __popc(myword);
            myword = 0;
        }
    }
    atomicAdd(&g_npi[jb*128 + tid], pcmy);
    if (ib != jb) {
        #pragma unroll
        for (int q = 0; q < 4; ++q) {
            g_pm[(size_t)(ib*128 + q*32 + lane) * 128 + jb*4 + wid] = tw[q];
            atomicAdd(&g_npi[ib*128 + q*32 + lane], __popc(tw[q]));
        }
    }
}

// ---------------- kernel 3: bf16 mma GEMM — explicit fragment pipeline, 1 CTA/SM ----------------
// 256 threads, 8 warps (4m x 2n), warp tile 32x32. 128 blocks x 32 col-tiles, jb fixed.
#define SM_A     0
#define SM_B     8704
#define BSTRIDE  4352
#define SM_PM    21760
#define PMSTRIDE 256
#define SMEM_U32 22528

__device__ __forceinline__ void ld_tileA(uint32_t sb, int jb, int tid) {
    const uint32_t* Asrc = (const uint32_t*)g_Zh + (size_t)jb * 128 * 64;
    #pragma unroll
    for (int it = 0; it < 8; ++it) {
        int idx = it * 256 + tid;
        int r = idx >> 4, gr = idx & 15;
        cpa16(sb + (uint32_t)(r * PB + gr * 4) * 4u, Asrc + r * 64 + gr * 4);
    }
}
__device__ __forceinline__ void ld_tileB(uint32_t sb, int buf, int ct, int jb, int tid) {
    const uint32_t* Bsrc = (const uint32_t*)g_Zh + (size_t)ct * 64 * 64;
    uint32_t bo = sb + (SM_B + buf * BSTRIDE) * 4u;
    #pragma unroll
    for (int it = 0; it < 4; ++it) {
        int idx = it * 256 + tid;
        int r = idx >> 4, gr = idx & 15;
        cpa16(bo + (uint32_t)(r * PB + gr * 4) * 4u, Bsrc + r * 64 + gr * 4);
    }
    if (tid < 128)
        cpa8(sb + (SM_PM + buf * PMSTRIDE + tid * 2) * 4u,
             g_pm + (size_t)(jb * 128 + tid) * 128 + (ct & 63) * 2);
}

__global__ void __launch_bounds__(256) kmain(float* __restrict__ out) {
    extern __shared__ uint32_t sm32[];
    const int tid  = threadIdx.x;
    const int lane = tid & 31, wid = tid >> 5;
    const int wm   = wid >> 1, wn = wid & 1;      // 4 m-warps x 2 n-warps
    const int g    = lane >> 2, tg = lane & 3;

    const int jb  = blockIdx.x >> 2;              // anchor tile (128 rows)
    const int ct0 = (blockIdx.x & 3) * 32;        // 32 col-tiles of width 64

    uint32_t sb = smem_u32(sm32);

    const int grp = lane >> 3, lrow = lane & 7;
    const uint32_t addrA0 = sb + ((wm * 32 + (grp & 1) * 8 + lrow) * PB + (grp >> 1) * 4) * 4u;
    const uint32_t addrA1 = addrA0 + 16 * PB * 4u;
    const uint32_t boffB  = ((wn * 32 + (grp >> 1) * 8 + lrow) * PB + (grp & 1) * 4) * 4u;

    ld_tileA(sb, jb, tid);
    ld_tileB(sb, 0, ct0, jb, tid);
    CP_COMMIT();
    ld_tileB(sb, 1, ct0 + 1, jb, tid);
    CP_COMMIT();
    CP_WAIT1();
    __syncthreads();

    float se[4] = {0,0,0,0}, pv[4] = {0,0,0,0};

    int buf = 0;
    #pragma unroll 1
    for (int t = 0; t < 32; ++t) {
        const int ct = ct0 + t;
        if (t + 2 < 32) { ld_tileB(sb, (buf + 2) % 3, ct + 2, jb, tid); CP_COMMIT(); }

        float d[2][4][4];
        #pragma unroll
        for (int mf = 0; mf < 2; ++mf)
            #pragma unroll
            for (int nf = 0; nf < 4; ++nf)
                #pragma unroll
                for (int q = 0; q < 4; ++q) d[mf][nf][q] = 0.0f;

        const uint32_t addrB0 = sb + (SM_B + buf * BSTRIDE) * 4u + boffB;
        const uint32_t addrB1 = addrB0 + 16 * PB * 4u;

        // ---- explicit fragment double-buffered K loop ----
        uint32_t fa0[2][4], fa1[2][4], fbA[2][4], fbB[2][4];
        ldsm_x4(fa0[0], addrA0);
        ldsm_x4(fa1[0], addrA1);
        ldsm_x4(fbA[0], addrB0);
        ldsm_x4(fbB[0], addrB1);
        #pragma unroll
        for (int ks = 0; ks < 8; ++ks) {
            const int cur = ks & 1, nxt = cur ^ 1;
            if (ks < 7) {
                ldsm_x4(fa0[nxt], addrA0 + (ks + 1) * 32u);
                ldsm_x4(fa1[nxt], addrA1 + (ks + 1) * 32u);
                ldsm_x4(fbA[nxt], addrB0 + (ks + 1) * 32u);
                ldsm_x4(fbB[nxt], addrB1 + (ks + 1) * 32u);
            }
            mma_bf16(d[0][0], fa0[cur], fbA[cur] + 0);
            mma_bf16(d[0][1], fa0[cur], fbA[cur] + 2);
            mma_bf16(d[0][2], fa0[cur], fbB[cur] + 0);
            mma_bf16(d[0][3], fa0[cur], fbB[cur] + 2);
            mma_bf16(d[1][0], fa1[cur], fbA[cur] + 0);
            mma_bf16(d[1][1], fa1[cur], fbA[cur] + 2);
            mma_bf16(d[1][2], fa1[cur], fbB[cur] + 0);
            mma_bf16(d[1][3], fa1[cur], fbB[cur] + 2);
        }

        // ---- fused epilogue (diag/aug-specialized) ----
        const unsigned* pmS = sm32 + SM_PM + buf * PMSTRIDE;
        const int c0 = ct * 64;
        const bool special = ((ct >> 1) == jb) | ((ct >> 1) == jb + 32);
        if (!special) {
            #pragma unroll
            for (int mf = 0; mf < 2; ++mf) {
                #pragma unroll
                for (int h = 0; h < 2; ++h) {
                    const int rl = wm * 32 + mf * 16 + h * 8 + g;
                    const int ai = mf * 2 + h;
                    float a_se = 0.f, a_pv = 0.f;
                    #pragma unroll
                    for (int nf = 0; nf < 4; ++nf) {
                        const int cl = wn * 32 + nf * 8 + tg * 2;
                        const unsigned w = pmS[rl * 2 + (cl >> 5)];
                        #pragma unroll
                        for (int q = 0; q < 2; ++q) {
                            float v = d[mf][nf][h * 2 + q];
                            a_se += ex2(fmaf(v, C1, C2));
                            if ((w >> ((cl + q) & 31)) & 1u) a_pv += v;
                        }
                    }
                    se[ai] += a_se; pv[ai] += a_pv;
                }
            }
        } else {
            #pragma unroll
            for (int mf = 0; mf < 2; ++mf) {
                #pragma unroll
                for (int h = 0; h < 2; ++h) {
                    const int rl   = wm * 32 + mf * 16 + h * 8 + g;
                    const int jr   = jb * 128 + rl;
                    const int jaug = jr + NROWS;
                    const int ai   = mf * 2 + h;
                    float a_se = 0.f, a_pv = 0.f;
                    #pragma unroll
                    for (int nf = 0; nf < 4; ++nf) {
                        const int cl = wn * 32 + nf * 8 + tg * 2;
                        const unsigned w = pmS[rl * 2 + (cl >> 5)];
                        #pragma unroll
                        for (int q = 0; q < 2; ++q) {
                            const int cg = c0 + cl + q;
                            float v = d[mf][nf][h * 2 + q];
                            float e = ex2(fmaf(v, C1, C2));
                            bool pos = (((w >> ((cl + q) & 31)) & 1u) != 0u) | (cg == jaug);
                            if (cg != jr) {
                                a_se += e;
                                if (pos) a_pv += v;
                            }
                        }
                    }
                    se[ai] += a_se; pv[ai] += a_pv;
                }
            }
        }

        if (t + 2 < 32) CP_WAIT1();
        else            CP_WAIT0();
        __syncthreads();
        buf = (buf + 1) % 3;
    }

    // ---- flush (4 blocks per jb) ----
    #pragma unroll
    for (int ai = 0; ai < 4; ++ai) {
        float a = se[ai], b = pv[ai];
        a += __shfl_xor_sync(0xffffffffu, a, 1); a += __shfl_xor_sync(0xffffffffu, a, 2);
        b += __shfl_xor_sync(0xffffffffu, b, 1); b += __shfl_xor_sync(0xffffffffu, b, 2);
        if (tg == 0) {
            int row = jb * 128 + wm * 32 + (ai >> 1) * 16 + (ai & 1) * 8 + g;
            atomicAdd(&g_se[row], a);
            atomicAdd(&g_pv[row], b);
        }
    }

    // ---- last block reduces ----
    __threadfence();
    __syncthreads();
    __shared__ unsigned ticket;
    if (tid == 0) ticket = atomicAdd(&g_done, 1u);
    __syncthreads();
    if (ticket == 127) {
        __shared__ float red[256];
        float s = 0.0f;
        for (int i = tid; i < NROWS; i += 256) {
            unsigned pmjj = (g_pm[(size_t)i * 128 + (i >> 5)] >> (i & 31)) & 1u;
            float np = (float)(2 * (g_npi[i] - (int)pmjj) + 1);   // >= 1
            float ps = INV_TAU * (g_pv[i] - np);
            s += -(ps - np * logf(g_se[i] + 1e-8f)) / np;
        }
        red[tid] = s;
        __syncthreads();
        for (int o = 128; o; o >>= 1) {
            if (tid < o) red[tid] += red[tid + o];
            __syncthreads();
        }
        if (tid == 0) out[0] = red[0] / (float)NROWS;
    }
}

// ---------------- launch ----------------
extern "C" void kernel_launch(void* const* d_in, const int* in_sizes, int n_in,
                              void* d_out, int out_size) {
    const float* z1     = (const float*)d_in[0];
    const float* z2     = (const float*)d_in[1];
    const int*   labels = (const int*)d_in[2];
    float* out = (float*)d_out;

    cudaFuncSetAttribute(kmain, cudaFuncAttributeMaxDynamicSharedMemorySize,
                         SMEM_U32 * 4);

    kprep<<<1536, 256>>>(z1, z2, labels);
    kjacc<<<528, 128>>>();
    kmain<<<128, 256, SMEM_U32 * 4>>>(out);
}

// round 15
// speedup vs baseline: 1.8475x; 1.0468x over previous
#include <cuda_runtime.h>
#include <cuda_bf16.h>
#include <cstdint>
#include <math.h>

#define NROWS 4096
#define D     128
#define AWORD 16
#define INV_TAU (1.0f/0.07f)
#define C1 ( 20.60992915555662f)   //  INV_TAU * log2(e)
#define C2 (-20.60992915555662f)
#define PB    68                   // smem row pitch in u32 (conflict-free)

// ---------------- static device scratch ----------------
__device__ __nv_bfloat16 g_Zh[2 * NROWS * D];
__device__ unsigned g_bits[NROWS * AWORD];
__device__ int      g_cnt[NROWS];
__device__ unsigned g_pm[NROWS * (NROWS/32)];
__device__ float    g_se[NROWS], g_pv[NROWS];
__device__ int      g_npi[NROWS];
__device__ unsigned g_done;

// ---------------- helpers ----------------
__device__ __forceinline__ uint32_t smem_u32(const void* p) {
    uint32_t a;
    asm("{ .reg .u64 t; cvta.to.shared.u64 t, %1; cvt.u32.u64 %0, t; }" : "=r"(a) : "l"(p));
    return a;
}
__device__ __forceinline__ void cpa16(uint32_t dst, const void* src) {
    asm volatile("cp.async.cg.shared.global [%0], [%1], 16;" :: "r"(dst), "l"(src));
}
__device__ __forceinline__ void cpa8(uint32_t dst, const void* src) {
    asm volatile("cp.async.ca.shared.global [%0], [%1], 8;" :: "r"(dst), "l"(src));
}
#define MBARRIER_INIT(a, c) \
    asm volatile("mbarrier.init.shared.b64 [%0], %1;" :: "r"(a), "r"(c) : "memory")
#define MBAR_ARRIVE(a) \
    asm volatile("mbarrier.arrive.shared.b64 _, [%0];" :: "r"(a) : "memory")
// .noinc: arrival COUNTS against the initialized expected count (non-noinc is phase-neutral!)
#define CPASYNC_MBAR_ARRIVE(a) \
    asm volatile("cp.async.mbarrier.arrive.noinc.shared.b64 [%0];" :: "r"(a) : "memory")
#define MBARRIER_WAIT_PARITY(a, ph) do {                                             \
    uint32_t _m = (a), _p = (ph), _d;                                                \
    asm volatile("{ .reg .pred p; mbarrier.try_wait.parity.acquire.cta.shared::cta.b64 p, [%1], %2; selp.b32 %0,1,0,p; }" \
        : "=r"(_d) : "r"(_m), "r"(_p) : "memory");                                   \
    if (!_d) {                                                                       \
        asm volatile("{ .reg .pred P; L%=: mbarrier.try_wait.parity.acquire.cta.shared::cta.b64 P, [%0], %1, 0x989680; @P bra D%=; bra L%=; D%=: }" \
            :: "r"(_m), "r"(_p) : "memory");                                         \
    } } while (0)

__device__ __forceinline__ float ex2(float x) {
    float r;
    asm("ex2.approx.f32 %0, %1;" : "=f"(r) : "f"(x));
    return r;
}
__device__ __forceinline__ void ldsm_x4(uint32_t* r, uint32_t addr) {
    asm volatile("ldmatrix.sync.aligned.m8n8.x4.shared.b16 {%0,%1,%2,%3}, [%4];"
        : "=r"(r[0]), "=r"(r[1]), "=r"(r[2]), "=r"(r[3]) : "r"(addr));
}
__device__ __forceinline__ void mma_bf16(float* d, const uint32_t* a, const uint32_t* b) {
    asm volatile(
        "mma.sync.aligned.m16n8k16.row.col.f32.bf16.bf16.f32 "
        "{%0,%1,%2,%3}, {%4,%5,%6,%7}, {%8,%9}, {%0,%1,%2,%3};"
        : "+f"(d[0]), "+f"(d[1]), "+f"(d[2]), "+f"(d[3])
        : "r"(a[0]), "r"(a[1]), "r"(a[2]), "r"(a[3]), "r"(b[0]), "r"(b[1]));
}

// ---------------- kernel 0: zero accumulators ----------------
__global__ void kzero() {
    int i = blockIdx.x * 256 + threadIdx.x;
    if (i == 0) g_done = 0;
    if (i < NROWS) { g_se[i] = 0.f; g_pv[i] = 0.f; g_npi[i] = 0; }
}

// ---------------- kernel 1: fused prep (normalize->bf16 / pack) ----------------
__global__ void kprep(const float* __restrict__ z1, const float* __restrict__ z2,
                      const int* __restrict__ labels) {
    const int tid  = threadIdx.x;
    const int wid  = tid >> 5;
    const int lane = tid & 31;

    if (blockIdx.x < 1024) {
        int r = blockIdx.x * 8 + wid;
        const float* src = (r < NROWS) ? (z1 + (size_t)r * D) : (z2 + (size_t)(r - NROWS) * D);
        float4 v = ((const float4*)src)[lane];
        float ss = v.x*v.x + v.y*v.y + v.z*v.z + v.w*v.w;
        #pragma unroll
        for (int o = 16; o; o >>= 1) ss += __shfl_xor_sync(0xffffffffu, ss, o);
        float inv = 1.0f / fmaxf(sqrtf(ss), 1e-12f);
        __nv_bfloat162 p0 = __floats2bfloat162_rn(v.x*inv, v.y*inv);
        __nv_bfloat162 p1 = __floats2bfloat162_rn(v.z*inv, v.w*inv);
        uint2 o2 = make_uint2(*(uint32_t*)&p0, *(uint32_t*)&p1);
        ((uint2*)g_Zh)[(size_t)r * 32 + lane] = o2;
    } else {
        int r = (blockIdx.x - 1024) * 8 + wid;
        const int* lp = labels + (size_t)r * 512;
        int cnt = 0; unsigned myw = 0;
        #pragma unroll
        for (int w = 0; w < AWORD; ++w) {
            unsigned word = __ballot_sync(0xffffffffu, lp[w * 32 + lane] != 0);
            if (lane == w) myw = word;
            cnt += __popc(word);
        }
        if (lane < AWORD) g_bits[r * AWORD + lane] = myw;
        if (lane == 0)    g_cnt[r] = cnt;
    }
}

// ---------------- kernel 2: jaccard pos mask + row popcounts (proven) ----------------
__global__ void __launch_bounds__(128) kjacc() {
    int rem = blockIdx.x, jb = 0;
    while (rem >= 32 - jb) { rem -= 32 - jb; ++jb; }
    int ib = jb + rem;

    __shared__ unsigned sib[128 * AWORD];
    __shared__ int      sci[128];

    int tid  = threadIdx.x;
    int lane = tid & 31, wid = tid >> 5;

    uint4 jr4[4];
    #pragma unroll
    for (int q = 0; q < 4; ++q)
        jr4[q] = ((const uint4*)(g_bits + (size_t)(jb*128 + tid) * AWORD))[q];
    const unsigned* jr = (const unsigned*)jr4;
    int sj = g_cnt[jb*128 + tid];
    #pragma unroll
    for (int q = 0; q < 4; ++q)
        ((uint4*)sib)[q * 128 + tid] = ((const uint4*)(g_bits + (size_t)ib * 128 * AWORD))[q * 128 + tid];
    sci[tid] = g_cnt[ib*128 + tid];
    __syncthreads();

    unsigned myword = 0;
    unsigned tw[4];
    int pcmy = 0;
    #pragma unroll 2
    for (int i0 = 0; i0 < 128; i0 += 2) {
        const unsigned* iwA = sib + i0 * AWORD;
        const unsigned* iwB = iwA + AWORD;
        int a0=0, a1=0, a2=0, a3=0, b0=0, b1=0, b2=0, b3=0;
        #pragma unroll
        for (int w = 0; w < 4; ++w) {
            a0 += __popc(jr[w]      & iwA[w]);
            a1 += __popc(jr[w + 4]  & iwA[w + 4]);
            a2 += __popc(jr[w + 8]  & iwA[w + 8]);
            a3 += __popc(jr[w + 12] & iwA[w + 12]);
            b0 += __popc(jr[w]      & iwB[w]);
            b1 += __popc(jr[w + 4]  & iwB[w + 4]);
            b2 += __popc(jr[w + 8]  & iwB[w + 8]);
            b3 += __popc(jr[w + 12] & iwB[w + 12]);
        }
        int iA = (a0 + a1) + (a2 + a3);
        int iB = (b0 + b1) + (b2 + b3);
        long long uA = (long long)(sj + sci[i0]     - iA);
        long long uB = (long long)(sj + sci[i0 + 1] - iB);
        bool posA = (iA > 0) && (((long long)iA << 26) >= 20132659LL * uA);
        bool posB = (iB > 0) && (((long long)iB << 26) >= 20132659LL * uB);
        myword |= (posA ? 1u : 0u) << (i0 & 31);
        myword |= (posB ? 1u : 0u) << ((i0 + 1) & 31);
        unsigned balA = __ballot_sync(0xffffffffu, posA);
        unsigned balB = __ballot_sync(0xffffffffu, posB);
        if ((i0 & 31) == lane)       tw[i0 >> 5] = balA;
        if (((i0 + 1) & 31) == lane) tw[i0 >> 5] = balB;
        if ((i0 & 31) == 30) {
            g_pm[(size_t)(jb*128 + tid) * 128 + ib*4 + (i0 >> 5)] = myword;
            pcmy += __popc(myword);
            myword = 0;
        }
    }
    atomicAdd(&g_npi[jb*128 + tid], pcmy);
    if (ib != jb) {
        #pragma unroll
        for (int q = 0; q < 4; ++q) {
            g_pm[(size_t)(ib*128 + q*32 + lane) * 128 + jb*4 + wid] = tw[q];
            atomicAdd(&g_npi[ib*128 + q*32 + lane], __popc(tw[q]));
        }
    }
}

// ---------------- kernel 3: bf16 mma GEMM — mbarrier ring, free-running warps ----------------
// 256 threads, 8 warps (4m x 2n), warp tile 32x32. 256 blocks (2/SM), 16 col-tiles each.
#define SM_A     0
#define SM_B     8704
#define BSTRIDE  4352
#define SM_PM    21760
#define PMSTRIDE 256
#define SM_MBAR  22528
#define SMEM_U32 22540

__device__ __forceinline__ void ld_tileA(uint32_t sb, int jb, int tid) {
    const uint32_t* Asrc = (const uint32_t*)g_Zh + (size_t)jb * 128 * 64;
    #pragma unroll
    for (int it = 0; it < 8; ++it) {
        int idx = it * 256 + tid;
        int r = idx >> 4, gr = idx & 15;
        cpa16(sb + (uint32_t)(r * PB + gr * 4) * 4u, Asrc + r * 64 + gr * 4);
    }
}
__device__ __forceinline__ void ld_tileB(uint32_t sb, int buf, int ct, int jb, int tid) {
    const uint32_t* Bsrc = (const uint32_t*)g_Zh + (size_t)ct * 64 * 64;
    uint32_t bo = sb + (SM_B + buf * BSTRIDE) * 4u;
    #pragma unroll
    for (int it = 0; it < 4; ++it) {
        int idx = it * 256 + tid;
        int r = idx >> 4, gr = idx & 15;
        cpa16(bo + (uint32_t)(r * PB + gr * 4) * 4u, Bsrc + r * 64 + gr * 4);
    }
    if (tid < 128)
        cpa8(sb + (SM_PM + buf * PMSTRIDE + tid * 2) * 4u,
             g_pm + (size_t)(jb * 128 + tid) * 128 + (ct & 63) * 2);
}

__global__ void __launch_bounds__(256, 2) kmain(float* __restrict__ out) {
    extern __shared__ uint32_t sm32[];
    const int tid  = threadIdx.x;
    const int lane = tid & 31, wid = tid >> 5;
    const int wm   = wid >> 1, wn = wid & 1;      // 4 m-warps x 2 n-warps
    const int g    = lane >> 2, tg = lane & 3;

    const int jb  = blockIdx.x >> 3;              // anchor tile (128 rows)
    const int ct0 = (blockIdx.x & 7) * 16;        // 16 col-tiles of width 64

    uint32_t sb = smem_u32(sm32);
    const uint32_t mb = sb + SM_MBAR * 4u;        // full[b]=mb+b*16, empty[b]=mb+b*16+8

    if (tid == 0) {
        #pragma unroll
        for (int b = 0; b < 3; ++b) {
            MBARRIER_INIT(mb + b * 16,     256);
            MBARRIER_INIT(mb + b * 16 + 8, 256);
        }
    }
    __syncthreads();

    const int grp = lane >> 3, lrow = lane & 7;
    const uint32_t addrA0 = sb + ((wm * 32 + (grp & 1) * 8 + lrow) * PB + (grp >> 1) * 4) * 4u;
    const uint32_t addrA1 = addrA0 + 16 * PB * 4u;
    const uint32_t boffB  = ((wn * 32 + (grp >> 1) * 8 + lrow) * PB + (grp & 1) * 4) * 4u;

    // prologue: A + B0 -> full[0] (arrival covers A too), B1 -> full[1]
    ld_tileA(sb, jb, tid);
    ld_tileB(sb, 0, ct0, jb, tid);
    CPASYNC_MBAR_ARRIVE(mb + 0 * 16);
    ld_tileB(sb, 1, ct0 + 1, jb, tid);
    CPASYNC_MBAR_ARRIVE(mb + 1 * 16);

    float se[4] = {0,0,0,0}, pv[4] = {0,0,0,0};

    #pragma unroll 1
    for (int t = 0; t < 16; ++t) {
        const int ct = ct0 + t;
        const int b  = t % 3;
        MBARRIER_WAIT_PARITY(mb + b * 16, (t / 3) & 1);          // tile t data ready

        const int f = t + 2;                                      // prefetch tile f
        if (f < 16) {
            const int fb = f % 3;
            if (f >= 3)
                MBARRIER_WAIT_PARITY(mb + fb * 16 + 8, ((f / 3) - 1) & 1); // tile f-3 consumed
            ld_tileB(sb, fb, ct0 + f, jb, tid);
            CPASYNC_MBAR_ARRIVE(mb + fb * 16);
        }

        float d[2][4][4];
        #pragma unroll
        for (int mf = 0; mf < 2; ++mf)
            #pragma unroll
            for (int nf = 0; nf < 4; ++nf)
                #pragma unroll
                for (int q = 0; q < 4; ++q) d[mf][nf][q] = 0.0f;

        const uint32_t addrB0 = sb + (SM_B + b * BSTRIDE) * 4u + boffB;
        const uint32_t addrB1 = addrB0 + 16 * PB * 4u;

        #pragma unroll
        for (int ks = 0; ks < 8; ++ks) {
            uint32_t a0[4], a1[4], bA[4], bB[4];
            ldsm_x4(a0, addrA0 + ks * 32u);
            ldsm_x4(a1, addrA1 + ks * 32u);
            ldsm_x4(bA, addrB0 + ks * 32u);
            ldsm_x4(bB, addrB1 + ks * 32u);
            mma_bf16(d[0][0], a0, bA + 0);
            mma_bf16(d[0][1], a0, bA + 2);
            mma_bf16(d[0][2], a0, bB + 0);
            mma_bf16(d[0][3], a0, bB + 2);
            mma_bf16(d[1][0], a1, bA + 0);
            mma_bf16(d[1][1], a1, bA + 2);
            mma_bf16(d[1][2], a1, bB + 0);
            mma_bf16(d[1][3], a1, bB + 2);
        }

        // ---- fused epilogue ----
        const unsigned* pmS = sm32 + SM_PM + b * PMSTRIDE;
        const int c0 = ct * 64;
        #pragma unroll
        for (int mf = 0; mf < 2; ++mf) {
            #pragma unroll
            for (int h = 0; h < 2; ++h) {
                const int rl   = wm * 32 + mf * 16 + h * 8 + g;
                const int jr   = jb * 128 + rl;
                const int jaug = jr + NROWS;
                const int ai   = mf * 2 + h;
                float a_se = 0.f, a_pv = 0.f;
                #pragma unroll
                for (int nf = 0; nf < 4; ++nf) {
                    const int cl = wn * 32 + nf * 8 + tg * 2;
                    const unsigned w = pmS[rl * 2 + (cl >> 5)];
                    #pragma unroll
                    for (int q = 0; q < 2; ++q) {
                        const int cg = c0 + cl + q;
                        float v = d[mf][nf][h * 2 + q];
                        float e = ex2(fmaf(v, C1, C2));
                        bool pos = (((w >> ((cl + q) & 31)) & 1u) != 0u) | (cg == jaug);
                        if (cg != jr) {
                            a_se += e;
                            if (pos) a_pv += v;
                        }
                    }
                }
                se[ai] += a_se; pv[ai] += a_pv;
            }
        }

        MBAR_ARRIVE(mb + b * 16 + 8);            // tile t consumed by this thread
    }

    // ---- flush (8 blocks per jb) ----
    #pragma unroll
    for (int ai = 0; ai < 4; ++ai) {
        float a = se[ai], b = pv[ai];
        a += __shfl_xor_sync(0xffffffffu, a, 1); a += __shfl_xor_sync(0xffffffffu, a, 2);
        b += __shfl_xor_sync(0xffffffffu, b, 1); b += __shfl_xor_sync(0xffffffffu, b, 2);
        if (tg == 0) {
            int row = jb * 128 + wm * 32 + (ai >> 1) * 16 + (ai & 1) * 8 + g;
            atomicAdd(&g_se[row], a);
            atomicAdd(&g_pv[row], b);
        }
    }

    // ---- last block reduces ----
    __threadfence();
    __syncthreads();
    __shared__ unsigned ticket;
    if (tid == 0) ticket = atomicAdd(&g_done, 1u);
    __syncthreads();
    if (ticket == 255) {
        __shared__ float red[256];
        float s = 0.0f;
        for (int i = tid; i < NROWS; i += 256) {
            unsigned pmjj = (g_pm[(size_t)i * 128 + (i >> 5)] >> (i & 31)) & 1u;
            float np = (float)(2 * (g_npi[i] - (int)pmjj) + 1);   // >= 1
            float ps = INV_TAU * (g_pv[i] - np);
            s += -(ps - np * logf(g_se[i] + 1e-8f)) / np;
        }
        red[tid] = s;
        __syncthreads();
        for (int o = 128; o; o >>= 1) {
            if (tid < o) red[tid] += red[tid + o];
            __syncthreads();
        }
        if (tid == 0) out[0] = red[0] / (float)NROWS;
    }
}

// ---------------- launch ----------------
extern "C" void kernel_launch(void* const* d_in, const int* in_sizes, int n_in,
                              void* d_out, int out_size) {
    const float* z1     = (const float*)d_in[0];
    const float* z2     = (const float*)d_in[1];
    const int*   labels = (const int*)d_in[2];
    float* out = (float*)d_out;

    cudaFuncSetAttribute(kmain, cudaFuncAttributeMaxDynamicSharedMemorySize,
                         SMEM_U32 * 4);

    kzero<<<16, 256>>>();
    kprep<<<1536, 256>>>(z1, z2, labels);
    kjacc<<<528, 128>>>();
    kmain<<<256, 256, SMEM_U32 * 4>>>(out);   // ncu profiles launch index 3 = kmain
}

// round 16
// speedup vs baseline: 1.8749x; 1.0148x over previous
#include <cuda_runtime.h>
#include <cuda_bf16.h>
#include <cstdint>
#include <math.h>

#define NROWS 4096
#define D     128
#define AWORD 16
#define INV_TAU (1.0f/0.07f)
#define C1 ( 20.60992915555662f)   //  INV_TAU * log2(e)
#define C2 (-20.60992915555662f)
#define PB    68                   // smem row pitch in u32 (conflict-free)

// ---------------- static device scratch ----------------
__device__ __nv_bfloat16 g_Zh[2 * NROWS * D];
__device__ unsigned g_bits[NROWS * AWORD];
__device__ int      g_cnt[NROWS];
__device__ unsigned g_pm[NROWS * (NROWS/32)];
__device__ float    g_se[NROWS], g_pv[NROWS];
__device__ int      g_npi[NROWS];
__device__ unsigned g_done;

// ---------------- helpers ----------------
__device__ __forceinline__ uint32_t smem_u32(const void* p) {
    uint32_t a;
    asm("{ .reg .u64 t; cvta.to.shared.u64 t, %1; cvt.u32.u64 %0, t; }" : "=r"(a) : "l"(p));
    return a;
}
__device__ __forceinline__ void cpa16(uint32_t dst, const void* src) {
    asm volatile("cp.async.cg.shared.global [%0], [%1], 16;" :: "r"(dst), "l"(src));
}
__device__ __forceinline__ void cpa8(uint32_t dst, const void* src) {
    asm volatile("cp.async.ca.shared.global [%0], [%1], 8;" :: "r"(dst), "l"(src));
}
#define CP_COMMIT() asm volatile("cp.async.commit_group;" ::: "memory")
#define CP_WAIT0()  asm volatile("cp.async.wait_group 0;" ::: "memory")
#define CP_WAIT1()  asm volatile("cp.async.wait_group 1;" ::: "memory")

__device__ __forceinline__ float ex2(float x) {
    float r;
    asm("ex2.approx.f32 %0, %1;" : "=f"(r) : "f"(x));
    return r;
}
__device__ __forceinline__ void ldsm_x4(uint32_t* r, uint32_t addr) {
    asm volatile("ldmatrix.sync.aligned.m8n8.x4.shared.b16 {%0,%1,%2,%3}, [%4];"
        : "=r"(r[0]), "=r"(r[1]), "=r"(r[2]), "=r"(r[3]) : "r"(addr));
}
__device__ __forceinline__ void mma_bf16(float* d, const uint32_t* a, const uint32_t* b) {
    asm volatile(
        "mma.sync.aligned.m16n8k16.row.col.f32.bf16.bf16.f32 "
        "{%0,%1,%2,%3}, {%4,%5,%6,%7}, {%8,%9}, {%0,%1,%2,%3};"
        : "+f"(d[0]), "+f"(d[1]), "+f"(d[2]), "+f"(d[3])
        : "r"(a[0]), "r"(a[1]), "r"(a[2]), "r"(a[3]), "r"(b[0]), "r"(b[1]));
}

// ---------------- kernel 0: zero accumulators (keeps ncu on kmain at idx 4) ----------------
__global__ void kzero() {
    int i = blockIdx.x * 256 + threadIdx.x;
    if (i == 0) g_done = 0;
    if (i < NROWS) { g_se[i] = 0.f; g_pv[i] = 0.f; g_npi[i] = 0; }
}

// ---------------- kernel 1: fused prep (normalize->bf16 / pack) ----------------
__global__ void kprep(const float* __restrict__ z1, const float* __restrict__ z2,
                      const int* __restrict__ labels) {
    const int tid  = threadIdx.x;
    const int wid  = tid >> 5;
    const int lane = tid & 31;

    if (blockIdx.x < 1024) {
        int r = blockIdx.x * 8 + wid;
        const float* src = (r < NROWS) ? (z1 + (size_t)r * D) : (z2 + (size_t)(r - NROWS) * D);
        float4 v = ((const float4*)src)[lane];
        float ss = v.x*v.x + v.y*v.y + v.z*v.z + v.w*v.w;
        #pragma unroll
        for (int o = 16; o; o >>= 1) ss += __shfl_xor_sync(0xffffffffu, ss, o);
        float inv = 1.0f / fmaxf(sqrtf(ss), 1e-12f);
        __nv_bfloat162 p0 = __floats2bfloat162_rn(v.x*inv, v.y*inv);
        __nv_bfloat162 p1 = __floats2bfloat162_rn(v.z*inv, v.w*inv);
        uint2 o2 = make_uint2(*(uint32_t*)&p0, *(uint32_t*)&p1);
        ((uint2*)g_Zh)[(size_t)r * 32 + lane] = o2;
    } else {
        int r = (blockIdx.x - 1024) * 8 + wid;
        const int* lp = labels + (size_t)r * 512;
        int cnt = 0; unsigned myw = 0;
        #pragma unroll
        for (int w = 0; w < AWORD; ++w) {
            unsigned word = __ballot_sync(0xffffffffu, lp[w * 32 + lane] != 0);
            if (lane == w) myw = word;
            cnt += __popc(word);
        }
        if (lane < AWORD) g_bits[r * AWORD + lane] = myw;
        if (lane == 0)    g_cnt[r] = cnt;
    }
}

// ---------------- kernel 2: jaccard pos mask + row popcounts — 4-way unroll ----------------
// pos <=> __fdiv_rn(inter, union) >= 0.3f  <=>  inter>0 && (inter<<26) >= 20132659*union
#define PAIRPOP(acc0, acc1, iw)                                  \
    do {                                                          \
        _Pragma("unroll")                                         \
        for (int w = 0; w < 8; ++w) {                             \
            acc0 += __popc(jr[w]     & (iw)[w]);                  \
            acc1 += __popc(jr[w + 8] & (iw)[w + 8]);              \
        }                                                         \
    } while (0)

__global__ void __launch_bounds__(128) kjacc() {
    int rem = blockIdx.x, jb = 0;
    while (rem >= 32 - jb) { rem -= 32 - jb; ++jb; }
    int ib = jb + rem;

    __shared__ unsigned sib[128 * AWORD];
    __shared__ int      sci[128];

    int tid  = threadIdx.x;
    int lane = tid & 31, wid = tid >> 5;

    uint4 jr4[4];
    #pragma unroll
    for (int q = 0; q < 4; ++q)
        jr4[q] = ((const uint4*)(g_bits + (size_t)(jb*128 + tid) * AWORD))[q];
    const unsigned* jr = (const unsigned*)jr4;
    int sj = g_cnt[jb*128 + tid];
    #pragma unroll
    for (int q = 0; q < 4; ++q)
        ((uint4*)sib)[q * 128 + tid] = ((const uint4*)(g_bits + (size_t)ib * 128 * AWORD))[q * 128 + tid];
    sci[tid] = g_cnt[ib*128 + tid];
    __syncthreads();

    unsigned myword = 0;
    unsigned tw[4];
    int pcmy = 0;
    #pragma unroll 2
    for (int i0 = 0; i0 < 128; i0 += 4) {
        const unsigned* iwA = sib + i0 * AWORD;
        const unsigned* iwB = iwA + AWORD;
        const unsigned* iwC = iwB + AWORD;
        const unsigned* iwD = iwC + AWORD;
        int a0=0,a1=0, b0=0,b1=0, c0=0,c1=0, d0=0,d1=0;
        PAIRPOP(a0, a1, iwA);
        PAIRPOP(b0, b1, iwB);
        PAIRPOP(c0, c1, iwC);
        PAIRPOP(d0, d1, iwD);
        int iA = a0 + a1, iB = b0 + b1, iC = c0 + c1, iD = d0 + d1;
        long long uA = (long long)(sj + sci[i0]     - iA);
        long long uB = (long long)(sj + sci[i0 + 1] - iB);
        long long uC = (long long)(sj + sci[i0 + 2] - iC);
        long long uD = (long long)(sj + sci[i0 + 3] - iD);
        bool posA = (iA > 0) && (((long long)iA << 26) >= 20132659LL * uA);
        bool posB = (iB > 0) && (((long long)iB << 26) >= 20132659LL * uB);
        bool posC = (iC > 0) && (((long long)iC << 26) >= 20132659LL * uC);
        bool posD = (iD > 0) && (((long long)iD << 26) >= 20132659LL * uD);
        myword |= (posA ? 1u : 0u) << ( i0      & 31);
        myword |= (posB ? 1u : 0u) << ((i0 + 1) & 31);
        myword |= (posC ? 1u : 0u) << ((i0 + 2) & 31);
        myword |= (posD ? 1u : 0u) << ((i0 + 3) & 31);
        unsigned balA = __ballot_sync(0xffffffffu, posA);
        unsigned balB = __ballot_sync(0xffffffffu, posB);
        unsigned balC = __ballot_sync(0xffffffffu, posC);
        unsigned balD = __ballot_sync(0xffffffffu, posD);
        if (( i0      & 31) == lane) tw[i0 >> 5] = balA;
        if (((i0 + 1) & 31) == lane) tw[i0 >> 5] = balB;
        if (((i0 + 2) & 31) == lane) tw[i0 >> 5] = balC;
        if (((i0 + 3) & 31) == lane) tw[i0 >> 5] = balD;
        if ((i0 & 31) == 28) {
            g_pm[(size_t)(jb*128 + tid) * 128 + ib*4 + (i0 >> 5)] = myword;
            pcmy += __popc(myword);
            myword = 0;
        }
    }
    atomicAdd(&g_npi[jb*128 + tid], pcmy);
    if (ib != jb) {
        #pragma unroll
        for (int q = 0; q < 4; ++q) {
            g_pm[(size_t)(ib*128 + q*32 + lane) * 128 + jb*4 + wid] = tw[q];
            atomicAdd(&g_npi[ib*128 + q*32 + lane], __popc(tw[q]));
        }
    }
}

// ---------------- kernel 3: bf16 mma GEMM — R11 proven core + specialized epilogue ----------------
// 256 threads, 8 warps (4m x 2n), warp tile 32x32. 256 blocks (2/SM), 16 col-tiles each.
#define SM_A     0
#define SM_B     8704
#define BSTRIDE  4352
#define SM_PM    21760
#define PMSTRIDE 256
#define SMEM_U32 22528

__device__ __forceinline__ void ld_tileA(uint32_t sb, int jb, int tid) {
    const uint32_t* Asrc = (const uint32_t*)g_Zh + (size_t)jb * 128 * 64;
    #pragma unroll
    for (int it = 0; it < 8; ++it) {
        int idx = it * 256 + tid;
        int r = idx >> 4, gr = idx & 15;
        cpa16(sb + (uint32_t)(r * PB + gr * 4) * 4u, Asrc + r * 64 + gr * 4);
    }
}
__device__ __forceinline__ void ld_tileB(uint32_t sb, int buf, int ct, int jb, int tid) {
    const uint32_t* Bsrc = (const uint32_t*)g_Zh + (size_t)ct * 64 * 64;
    uint32_t bo = sb + (SM_B + buf * BSTRIDE) * 4u;
    #pragma unroll
    for (int it = 0; it < 4; ++it) {
        int idx = it * 256 + tid;
        int r = idx >> 4, gr = idx & 15;
        cpa16(bo + (uint32_t)(r * PB + gr * 4) * 4u, Bsrc + r * 64 + gr * 4);
    }
    if (tid < 128)
        cpa8(sb + (SM_PM + buf * PMSTRIDE + tid * 2) * 4u,
             g_pm + (size_t)(jb * 128 + tid) * 128 + (ct & 63) * 2);
}

__global__ void __launch_bounds__(256, 2) kmain(float* __restrict__ out) {
    extern __shared__ uint32_t sm32[];
    const int tid  = threadIdx.x;
    const int lane = tid & 31, wid = tid >> 5;
    const int wm   = wid >> 1, wn = wid & 1;      // 4 m-warps x 2 n-warps
    const int g    = lane >> 2, tg = lane & 3;

    const int jb  = blockIdx.x >> 3;              // anchor tile (128 rows)
    const int ct0 = (blockIdx.x & 7) * 16;        // 16 col-tiles of width 64

    uint32_t sb = smem_u32(sm32);

    const int grp = lane >> 3, lrow = lane & 7;
    const uint32_t addrA0 = sb + ((wm * 32 + (grp & 1) * 8 + lrow) * PB + (grp >> 1) * 4) * 4u;
    const uint32_t addrA1 = addrA0 + 16 * PB * 4u;
    const uint32_t boffB  = ((wn * 32 + (grp >> 1) * 8 + lrow) * PB + (grp & 1) * 4) * 4u;

    ld_tileA(sb, jb, tid);
    ld_tileB(sb, 0, ct0, jb, tid);
    CP_COMMIT();
    ld_tileB(sb, 1, ct0 + 1, jb, tid);
    CP_COMMIT();
    CP_WAIT1();
    __syncthreads();

    float se[4] = {0,0,0,0}, pv[4] = {0,0,0,0};

    int buf = 0;
    #pragma unroll 1
    for (int t = 0; t < 16; ++t) {
        const int ct = ct0 + t;
        if (t + 2 < 16) { ld_tileB(sb, (buf + 2) % 3, ct + 2, jb, tid); CP_COMMIT(); }

        float d[2][4][4];
        #pragma unroll
        for (int mf = 0; mf < 2; ++mf)
            #pragma unroll
            for (int nf = 0; nf < 4; ++nf)
                #pragma unroll
                for (int q = 0; q < 4; ++q) d[mf][nf][q] = 0.0f;

        const uint32_t addrB0 = sb + (SM_B + buf * BSTRIDE) * 4u + boffB;
        const uint32_t addrB1 = addrB0 + 16 * PB * 4u;

        #pragma unroll
        for (int ks = 0; ks < 8; ++ks) {
            uint32_t a0[4], a1[4], bA[4], bB[4];
            ldsm_x4(a0, addrA0 + ks * 32u);
            ldsm_x4(a1, addrA1 + ks * 32u);
            ldsm_x4(bA, addrB0 + ks * 32u);
            ldsm_x4(bB, addrB1 + ks * 32u);
            mma_bf16(d[0][0], a0, bA + 0);
            mma_bf16(d[0][1], a0, bA + 2);
            mma_bf16(d[0][2], a0, bB + 0);
            mma_bf16(d[0][3], a0, bB + 2);
            mma_bf16(d[1][0], a1, bA + 0);
            mma_bf16(d[1][1], a1, bA + 2);
            mma_bf16(d[1][2], a1, bB + 0);
            mma_bf16(d[1][3], a1, bB + 2);
        }

        // ---- fused epilogue: lean path for 14/16 tiles, full path near diag/aug ----
        const unsigned* pmS = sm32 + SM_PM + buf * PMSTRIDE;
        const int c0 = ct * 64;
        const bool special = ((ct >> 1) == jb) | ((ct >> 1) == jb + 64);
        if (!special) {
            #pragma unroll
            for (int mf = 0; mf < 2; ++mf) {
                #pragma unroll
                for (int h = 0; h < 2; ++h) {
                    const int rl = wm * 32 + mf * 16 + h * 8 + g;
                    const int ai = mf * 2 + h;
                    float a_se = 0.f, a_pv = 0.f;
                    #pragma unroll
                    for (int nf = 0; nf < 4; ++nf) {
                        const int cl = wn * 32 + nf * 8 + tg * 2;
                        const unsigned w = pmS[rl * 2 + (cl >> 5)];
                        #pragma unroll
                        for (int q = 0; q < 2; ++q) {
                            float v = d[mf][nf][h * 2 + q];
                            a_se += ex2(fmaf(v, C1, C2));
                            if ((w >> ((cl + q) & 31)) & 1u) a_pv += v;
                        }
                    }
                    se[ai] += a_se; pv[ai] += a_pv;
                }
            }
        } else {
            #pragma unroll
            for (int mf = 0; mf < 2; ++mf) {
                #pragma unroll
                for (int h = 0; h < 2; ++h) {
                    const int rl   = wm * 32 + mf * 16 + h * 8 + g;
                    const int jr   = jb * 128 + rl;
                    const int jaug = jr + NROWS;
                    const int ai   = mf * 2 + h;
                    float a_se = 0.f, a_pv = 0.f;
                    #pragma unroll
                    for (int nf = 0; nf < 4; ++nf) {
                        const int cl = wn * 32 + nf * 8 + tg * 2;
                        const unsigned w = pmS[rl * 2 + (cl >> 5)];
                        #pragma unroll
                        for (int q = 0; q < 2; ++q) {
                            const int cg = c0 + cl + q;
                            float v = d[mf][nf][h * 2 + q];
                            float e = ex2(fmaf(v, C1, C2));
                            bool pos = (((w >> ((cl + q) & 31)) & 1u) != 0u) | (cg == jaug);
                            if (cg != jr) {
                                a_se += e;
                                if (pos) a_pv += v;
                            }
                        }
                    }
                    se[ai] += a_se; pv[ai] += a_pv;
                }
            }
        }

        CP_WAIT0();
        __syncthreads();
        buf = (buf + 1) % 3;
    }

    // ---- flush (8 blocks per jb) ----
    #pragma unroll
    for (int ai = 0; ai < 4; ++ai) {
        float a = se[ai], b = pv[ai];
        a += __shfl_xor_sync(0xffffffffu, a, 1); a += __shfl_xor_sync(0xffffffffu, a, 2);
        b += __shfl_xor_sync(0xffffffffu, b, 1); b += __shfl_xor_sync(0xffffffffu, b, 2);
        if (tg == 0) {
            int row = jb * 128 + wm * 32 + (ai >> 1) * 16 + (ai & 1) * 8 + g;
            atomicAdd(&g_se[row], a);
            atomicAdd(&g_pv[row], b);
        }
    }

    // ---- last block reduces ----
    __threadfence();
    __syncthreads();
    __shared__ unsigned ticket;
    if (tid == 0) ticket = atomicAdd(&g_done, 1u);
    __syncthreads();
    if (ticket == 255) {
        __shared__ float red[256];
        float s = 0.0f;
        for (int i = tid; i < NROWS; i += 256) {
            unsigned pmjj = (g_pm[(size_t)i * 128 + (i >> 5)] >> (i & 31)) & 1u;
            float np = (float)(2 * (g_npi[i] - (int)pmjj) + 1);   // >= 1
            float ps = INV_TAU * (g_pv[i] - np);
            s += -(ps - np * logf(g_se[i] + 1e-8f)) / np;
        }
        red[tid] = s;
        __syncthreads();
        for (int o = 128; o; o >>= 1) {
            if (tid < o) red[tid] += red[tid + o];
            __syncthreads();
        }
        if (tid == 0) out[0] = red[0] / (float)NROWS;
    }
}

// ---------------- launch ----------------
extern "C" void kernel_launch(void* const* d_in, const int* in_sizes, int n_in,
                              void* d_out, int out_size) {
    const float* z1     = (const float*)d_in[0];
    const float* z2     = (const float*)d_in[1];
    const int*   labels = (const int*)d_in[2];
    float* out = (float*)d_out;

    cudaFuncSetAttribute(kmain, cudaFuncAttributeMaxDynamicSharedMemorySize,
                         SMEM_U32 * 4);

    kzero<<<16, 256>>>();
    kprep<<<1536, 256>>>(z1, z2, labels);
    kjacc<<<528, 128>>>();
    kmain<<<256, 256, SMEM_U32 * 4>>>(out);
}

// round 17
// speedup vs baseline: 1.9643x; 1.0477x over previous
#include <cuda_runtime.h>
#include <cuda_bf16.h>
#include <cstdint>
#include <math.h>

#define NROWS 4096
#define D     128
#define AWORD 16
#define INV_TAU (1.0f/0.07f)
#define C1 ( 20.60992915555662f)   //  INV_TAU * log2(e)
#define C2 (-20.60992915555662f)
#define PB    68                   // smem row pitch in u32 (conflict-free)
#define NBLK  296                  // 2 CTAs x 148 SMs, balanced flat tile partition
#define NTILE 4096                 // 32 jb x 128 ct

// ---------------- static device scratch ----------------
__device__ __nv_bfloat16 g_Zh[2 * NROWS * D];
__device__ unsigned g_bits[NROWS * AWORD];
__device__ int      g_cnt[NROWS];
__device__ unsigned g_pm[NROWS * (NROWS/32)];
__device__ float    g_se[NROWS], g_pv[NROWS];
__device__ int      g_npi[NROWS];
__device__ unsigned g_done;

// ---------------- helpers ----------------
__device__ __forceinline__ uint32_t smem_u32(const void* p) {
    uint32_t a;
    asm("{ .reg .u64 t; cvta.to.shared.u64 t, %1; cvt.u32.u64 %0, t; }" : "=r"(a) : "l"(p));
    return a;
}
__device__ __forceinline__ void cpa16(uint32_t dst, const void* src) {
    asm volatile("cp.async.cg.shared.global [%0], [%1], 16;" :: "r"(dst), "l"(src));
}
__device__ __forceinline__ void cpa8(uint32_t dst, const void* src) {
    asm volatile("cp.async.ca.shared.global [%0], [%1], 8;" :: "r"(dst), "l"(src));
}
#define CP_COMMIT() asm volatile("cp.async.commit_group;" ::: "memory")
#define CP_WAIT0()  asm volatile("cp.async.wait_group 0;" ::: "memory")
#define CP_WAIT1()  asm volatile("cp.async.wait_group 1;" ::: "memory")

__device__ __forceinline__ float ex2(float x) {
    float r;
    asm("ex2.approx.f32 %0, %1;" : "=f"(r) : "f"(x));
    return r;
}
__device__ __forceinline__ void ldsm_x4(uint32_t* r, uint32_t addr) {
    asm volatile("ldmatrix.sync.aligned.m8n8.x4.shared.b16 {%0,%1,%2,%3}, [%4];"
        : "=r"(r[0]), "=r"(r[1]), "=r"(r[2]), "=r"(r[3]) : "r"(addr));
}
__device__ __forceinline__ void mma_bf16(float* d, const uint32_t* a, const uint32_t* b) {
    asm volatile(
        "mma.sync.aligned.m16n8k16.row.col.f32.bf16.bf16.f32 "
        "{%0,%1,%2,%3}, {%4,%5,%6,%7}, {%8,%9}, {%0,%1,%2,%3};"
        : "+f"(d[0]), "+f"(d[1]), "+f"(d[2]), "+f"(d[3])
        : "r"(a[0]), "r"(a[1]), "r"(a[2]), "r"(a[3]), "r"(b[0]), "r"(b[1]));
}

// ---------------- kernel 1: fused prep (normalize->bf16 / pack / zero) ----------------
__global__ void kprep(const float* __restrict__ z1, const float* __restrict__ z2,
                      const int* __restrict__ labels) {
    const int tid  = threadIdx.x;
    const int wid  = tid >> 5;
    const int lane = tid & 31;
    if (blockIdx.x == 0 && tid == 0) g_done = 0;

    if (blockIdx.x < 1024) {
        int r = blockIdx.x * 8 + wid;
        const float* src = (r < NROWS) ? (z1 + (size_t)r * D) : (z2 + (size_t)(r - NROWS) * D);
        float4 v = ((const float4*)src)[lane];
        float ss = v.x*v.x + v.y*v.y + v.z*v.z + v.w*v.w;
        #pragma unroll
        for (int o = 16; o; o >>= 1) ss += __shfl_xor_sync(0xffffffffu, ss, o);
        float inv = 1.0f / fmaxf(sqrtf(ss), 1e-12f);
        __nv_bfloat162 p0 = __floats2bfloat162_rn(v.x*inv, v.y*inv);
        __nv_bfloat162 p1 = __floats2bfloat162_rn(v.z*inv, v.w*inv);
        uint2 o2 = make_uint2(*(uint32_t*)&p0, *(uint32_t*)&p1);
        ((uint2*)g_Zh)[(size_t)r * 32 + lane] = o2;
    } else {
        int b2 = blockIdx.x - 1024;
        int r  = b2 * 8 + wid;
        int gidx = b2 * 256 + tid;
        if (gidx < NROWS) { g_se[gidx] = 0.f; g_pv[gidx] = 0.f; g_npi[gidx] = 0; }
        const int* lp = labels + (size_t)r * 512;
        int cnt = 0; unsigned myw = 0;
        #pragma unroll
        for (int w = 0; w < AWORD; ++w) {
            unsigned word = __ballot_sync(0xffffffffu, lp[w * 32 + lane] != 0);
            if (lane == w) myw = word;
            cnt += __popc(word);
        }
        if (lane < AWORD) g_bits[r * AWORD + lane] = myw;
        if (lane == 0)    g_cnt[r] = cnt;
    }
}

// ---------------- kernel 2: jaccard pos mask + row popcounts (proven) ----------------
#define PAIRPOP(acc0, acc1, iw)                                  \
    do {                                                          \
        _Pragma("unroll")                                         \
        for (int w = 0; w < 8; ++w) {                             \
            acc0 += __popc(jr[w]     & (iw)[w]);                  \
            acc1 += __popc(jr[w + 8] & (iw)[w + 8]);              \
        }                                                         \
    } while (0)

__global__ void __launch_bounds__(128) kjacc() {
    int rem = blockIdx.x, jb = 0;
    while (rem >= 32 - jb) { rem -= 32 - jb; ++jb; }
    int ib = jb + rem;

    __shared__ unsigned sib[128 * AWORD];
    __shared__ int      sci[128];

    int tid  = threadIdx.x;
    int lane = tid & 31, wid = tid >> 5;

    uint4 jr4[4];
    #pragma unroll
    for (int q = 0; q < 4; ++q)
        jr4[q] = ((const uint4*)(g_bits + (size_t)(jb*128 + tid) * AWORD))[q];
    const unsigned* jr = (const unsigned*)jr4;
    int sj = g_cnt[jb*128 + tid];
    #pragma unroll
    for (int q = 0; q < 4; ++q)
        ((uint4*)sib)[q * 128 + tid] = ((const uint4*)(g_bits + (size_t)ib * 128 * AWORD))[q * 128 + tid];
    sci[tid] = g_cnt[ib*128 + tid];
    __syncthreads();

    unsigned myword = 0;
    unsigned tw[4];
    int pcmy = 0;
    #pragma unroll 2
    for (int i0 = 0; i0 < 128; i0 += 4) {
        const unsigned* iwA = sib + i0 * AWORD;
        const unsigned* iwB = iwA + AWORD;
        const unsigned* iwC = iwB + AWORD;
        const unsigned* iwD = iwC + AWORD;
        int a0=0,a1=0, b0=0,b1=0, c0=0,c1=0, d0=0,d1=0;
        PAIRPOP(a0, a1, iwA);
        PAIRPOP(b0, b1, iwB);
        PAIRPOP(c0, c1, iwC);
        PAIRPOP(d0, d1, iwD);
        int iA = a0 + a1, iB = b0 + b1, iC = c0 + c1, iD = d0 + d1;
        long long uA = (long long)(sj + sci[i0]     - iA);
        long long uB = (long long)(sj + sci[i0 + 1] - iB);
        long long uC = (long long)(sj + sci[i0 + 2] - iC);
        long long uD = (long long)(sj + sci[i0 + 3] - iD);
        bool posA = (iA > 0) && (((long long)iA << 26) >= 20132659LL * uA);
        bool posB = (iB > 0) && (((long long)iB << 26) >= 20132659LL * uB);
        bool posC = (iC > 0) && (((long long)iC << 26) >= 20132659LL * uC);
        bool posD = (iD > 0) && (((long long)iD << 26) >= 20132659LL * uD);
        myword |= (posA ? 1u : 0u) << ( i0      & 31);
        myword |= (posB ? 1u : 0u) << ((i0 + 1) & 31);
        myword |= (posC ? 1u : 0u) << ((i0 + 2) & 31);
        myword |= (posD ? 1u : 0u) << ((i0 + 3) & 31);
        unsigned balA = __ballot_sync(0xffffffffu, posA);
        unsigned balB = __ballot_sync(0xffffffffu, posB);
        unsigned balC = __ballot_sync(0xffffffffu, posC);
        unsigned balD = __ballot_sync(0xffffffffu, posD);
        if (( i0      & 31) == lane) tw[i0 >> 5] = balA;
        if (((i0 + 1) & 31) == lane) tw[i0 >> 5] = balB;
        if (((i0 + 2) & 31) == lane) tw[i0 >> 5] = balC;
        if (((i0 + 3) & 31) == lane) tw[i0 >> 5] = balD;
        if ((i0 & 31) == 28) {
            g_pm[(size_t)(jb*128 + tid) * 128 + ib*4 + (i0 >> 5)] = myword;
            pcmy += __popc(myword);
            myword = 0;
        }
    }
    atomicAdd(&g_npi[jb*128 + tid], pcmy);
    if (ib != jb) {
        #pragma unroll
        for (int q = 0; q < 4; ++q) {
            g_pm[(size_t)(ib*128 + q*32 + lane) * 128 + jb*4 + wid] = tw[q];
            atomicAdd(&g_npi[ib*128 + q*32 + lane], __popc(tw[q]));
        }
    }
}

// ---------------- kernel 3: bf16 mma GEMM — balanced 296-block flat-tile partition ----------------
// 256 threads, 8 warps (4m x 2n), warp tile 32x32. Tile t: jb = t>>7, ct = t&127.
#define SM_A     0
#define SM_B     8704
#define BSTRIDE  4352
#define SM_PM    21760
#define PMSTRIDE 256
#define SMEM_U32 22528

__device__ __forceinline__ void ld_tileA(uint32_t sb, int jb, int tid) {
    const uint32_t* Asrc = (const uint32_t*)g_Zh + (size_t)jb * 128 * 64;
    #pragma unroll
    for (int it = 0; it < 8; ++it) {
        int idx = it * 256 + tid;
        int r = idx >> 4, gr = idx & 15;
        cpa16(sb + (uint32_t)(r * PB + gr * 4) * 4u, Asrc + r * 64 + gr * 4);
    }
}
// tile t: B rows [ (t&127)*64, +64 ) of z_all, pm words for jb = t>>7
__device__ __forceinline__ void ld_tileB(uint32_t sb, int buf, int t, int tid) {
    const int jb = t >> 7, ct = t & 127;
    const uint32_t* Bsrc = (const uint32_t*)g_Zh + (size_t)ct * 64 * 64;
    uint32_t bo = sb + (SM_B + buf * BSTRIDE) * 4u;
    #pragma unroll
    for (int it = 0; it < 4; ++it) {
        int idx = it * 256 + tid;
        int r = idx >> 4, gr = idx & 15;
        cpa16(bo + (uint32_t)(r * PB + gr * 4) * 4u, Bsrc + r * 64 + gr * 4);
    }
    if (tid < 128)
        cpa8(sb + (SM_PM + buf * PMSTRIDE + tid * 2) * 4u,
             g_pm + (size_t)(jb * 128 + tid) * 128 + (ct & 63) * 2);
}

__global__ void __launch_bounds__(256, 2) kmain(float* __restrict__ out) {
    extern __shared__ uint32_t sm32[];
    const int tid  = threadIdx.x;
    const int lane = tid & 31, wid = tid >> 5;
    const int wm   = wid >> 1, wn = wid & 1;      // 4 m-warps x 2 n-warps
    const int g    = lane >> 2, tg = lane & 3;

    const int t0 = (blockIdx.x * NTILE) / NBLK;
    const int t1 = ((blockIdx.x + 1) * NTILE) / NBLK;

    uint32_t sb = smem_u32(sm32);

    const int grp = lane >> 3, lrow = lane & 7;
    const uint32_t addrA0 = sb + ((wm * 32 + (grp & 1) * 8 + lrow) * PB + (grp >> 1) * 4) * 4u;
    const uint32_t addrA1 = addrA0 + 16 * PB * 4u;
    const uint32_t boffB  = ((wn * 32 + (grp >> 1) * 8 + lrow) * PB + (grp & 1) * 4) * 4u;

    int cur_jb = t0 >> 7;
    ld_tileA(sb, cur_jb, tid);
    ld_tileB(sb, 0, t0, tid);
    CP_COMMIT();
    ld_tileB(sb, 1, t0 + 1, tid);
    CP_COMMIT();
    CP_WAIT1();                 // A + B(t0) ready; B(t0+1) may be in flight
    __syncthreads();

    float se[4] = {0,0,0,0}, pv[4] = {0,0,0,0};

    #pragma unroll 1
    for (int t = t0; t < t1; ++t) {
        const int jb = t >> 7, ct = t & 127;
        const int buf = (t - t0) % 3;
        bool boundary = (jb != cur_jb);

        if (boundary) {
            // flush previous jb (previous iteration ended with __syncthreads)
            #pragma unroll
            for (int ai = 0; ai < 4; ++ai) {
                float a = se[ai], b2 = pv[ai];
                a  += __shfl_xor_sync(0xffffffffu, a, 1);  a  += __shfl_xor_sync(0xffffffffu, a, 2);
                b2 += __shfl_xor_sync(0xffffffffu, b2, 1); b2 += __shfl_xor_sync(0xffffffffu, b2, 2);
                if (tg == 0) {
                    int row = cur_jb * 128 + wm * 32 + (ai >> 1) * 16 + (ai & 1) * 8 + g;
                    atomicAdd(&g_se[row], a);
                    atomicAdd(&g_pv[row], b2);
                }
                se[ai] = 0.f; pv[ai] = 0.f;
            }
            cur_jb = jb;
            ld_tileA(sb, jb, tid);
            CP_COMMIT();
        }
        if (t + 2 < t1) { ld_tileB(sb, (t + 2 - t0) % 3, t + 2, tid); CP_COMMIT(); }
        if (boundary) { CP_WAIT1(); __syncthreads(); }   // new A (and B(t),B(t+1)) ready

        float d[2][4][4];
        #pragma unroll
        for (int mf = 0; mf < 2; ++mf)
            #pragma unroll
            for (int nf = 0; nf < 4; ++nf)
                #pragma unroll
                for (int q = 0; q < 4; ++q) d[mf][nf][q] = 0.0f;

        const uint32_t addrB0 = sb + (SM_B + buf * BSTRIDE) * 4u + boffB;
        const uint32_t addrB1 = addrB0 + 16 * PB * 4u;

        #pragma unroll
        for (int ks = 0; ks < 8; ++ks) {
            uint32_t a0[4], a1[4], bA[4], bB[4];
            ldsm_x4(a0, addrA0 + ks * 32u);
            ldsm_x4(a1, addrA1 + ks * 32u);
            ldsm_x4(bA, addrB0 + ks * 32u);
            ldsm_x4(bB, addrB1 + ks * 32u);
            mma_bf16(d[0][0], a0, bA + 0);
            mma_bf16(d[0][1], a0, bA + 2);
            mma_bf16(d[0][2], a0, bB + 0);
            mma_bf16(d[0][3], a0, bB + 2);
            mma_bf16(d[1][0], a1, bA + 0);
            mma_bf16(d[1][1], a1, bA + 2);
            mma_bf16(d[1][2], a1, bB + 0);
            mma_bf16(d[1][3], a1, bB + 2);
        }

        // ---- fused epilogue ----
        // lean path everywhere except the diagonal tile (self-exclusion).
        // aug column needs no special case: pm[j][j]=1 (Jaccard(j,j)=1>=0.3) supplies the
        // forced positive, and kfinal's np = 2*(npi - pmjj) + 1 accounts for it.
        const unsigned* pmS = sm32 + SM_PM + buf * PMSTRIDE;
        if ((ct >> 1) != jb) {
            #pragma unroll
            for (int mf = 0; mf < 2; ++mf) {
                #pragma unroll
                for (int h = 0; h < 2; ++h) {
                    const int rl = wm * 32 + mf * 16 + h * 8 + g;
                    const int ai = mf * 2 + h;
                    float a_se = 0.f, a_pv = 0.f;
                    #pragma unroll
                    for (int nf = 0; nf < 4; ++nf) {
                        const int cl = wn * 32 + nf * 8 + tg * 2;
                        const unsigned w = pmS[rl * 2 + (cl >> 5)];
                        #pragma unroll
                        for (int q = 0; q < 2; ++q) {
                            float v = d[mf][nf][h * 2 + q];
                            a_se += ex2(fmaf(v, C1, C2));
                            if ((w >> ((cl + q) & 31)) & 1u) a_pv += v;
                        }
                    }
                    se[ai] += a_se; pv[ai] += a_pv;
                }
            }
        } else {
            const int c0 = ct * 64;
            #pragma unroll
            for (int mf = 0; mf < 2; ++mf) {
                #pragma unroll
                for (int h = 0; h < 2; ++h) {
                    const int rl = wm * 32 + mf * 16 + h * 8 + g;
                    const int jr = jb * 128 + rl;
                    const int ai = mf * 2 + h;
                    float a_se = 0.f, a_pv = 0.f;
                    #pragma unroll
                    for (int nf = 0; nf < 4; ++nf) {
                        const int cl = wn * 32 + nf * 8 + tg * 2;
                        const unsigned w = pmS[rl * 2 + (cl >> 5)];
                        #pragma unroll
                        for (int q = 0; q < 2; ++q) {
                            const int cg = c0 + cl + q;
                            float v = d[mf][nf][h * 2 + q];
                            float e = ex2(fmaf(v, C1, C2));
                            if (cg != jr) {
                                a_se += e;
                                if ((w >> ((cl + q) & 31)) & 1u) a_pv += v;
                            }
                        }
                    }
                    se[ai] += a_se; pv[ai] += a_pv;
                }
            }
        }

        CP_WAIT1();
        __syncthreads();
    }

    // ---- final flush ----
    #pragma unroll
    for (int ai = 0; ai < 4; ++ai) {
        float a = se[ai], b2 = pv[ai];
        a  += __shfl_xor_sync(0xffffffffu, a, 1);  a  += __shfl_xor_sync(0xffffffffu, a, 2);
        b2 += __shfl_xor_sync(0xffffffffu, b2, 1); b2 += __shfl_xor_sync(0xffffffffu, b2, 2);
        if (tg == 0) {
            int row = cur_jb * 128 + wm * 32 + (ai >> 1) * 16 + (ai & 1) * 8 + g;
            atomicAdd(&g_se[row], a);
            atomicAdd(&g_pv[row], b2);
        }
    }

    // ---- last block reduces ----
    __threadfence();
    __syncthreads();
    __shared__ unsigned ticket;
    if (tid == 0) ticket = atomicAdd(&g_done, 1u);
    __syncthreads();
    if (ticket == NBLK - 1) {
        __shared__ float red[256];
        float s = 0.0f;
        for (int i = tid; i < NROWS; i += 256) {
            unsigned pmjj = (g_pm[(size_t)i * 128 + (i >> 5)] >> (i & 31)) & 1u;
            float np = (float)(2 * (g_npi[i] - (int)pmjj) + 1);   // >= 1
            float ps = INV_TAU * (g_pv[i] - np);
            s += -(ps - np * logf(g_se[i] + 1e-8f)) / np;
        }
        red[tid] = s;
        __syncthreads();
        for (int o = 128; o; o >>= 1) {
            if (tid < o) red[tid] += red[tid + o];
            __syncthreads();
        }
        if (tid == 0) out[0] = red[0] / (float)NROWS;
    }
}

// ---------------- launch ----------------
extern "C" void kernel_launch(void* const* d_in, const int* in_sizes, int n_in,
                              void* d_out, int out_size) {
    const float* z1     = (const float*)d_in[0];
    const float* z2     = (const float*)d_in[1];
    const int*   labels = (const int*)d_in[2];
    float* out = (float*)d_out;

    cudaFuncSetAttribute(kmain, cudaFuncAttributeMaxDynamicSharedMemorySize,
                         SMEM_U32 * 4);

    kprep<<<1536, 256>>>(z1, z2, labels);
    kjacc<<<528, 128>>>();
    kmain<<<NBLK, 256, SMEM_U32 * 4>>>(out);
}